// round 8
// baseline (speedup 1.0000x reference)
#include <cuda_runtime.h>
#include <cuda_fp16.h>

#define N_VOX 400000
#define C 32
#define K_TAPS 27
#define FULL 0xffffffffu

// W smem layout: half, row per (k,cout), pitch 40 halfs = 80B (16B-aligned,
// conflict-free LDS.128).
#define W_PITCH_H 40
#define SMEM_W_BYTES (K_TAPS * 32 * W_PITCH_H * 2)   // 69,120 B

// Static device scratch (no allocations allowed).
__device__ __half g_h  [(size_t)N_VOX * C];          // conv1 output (fp16)
__device__ __half g_x16[(size_t)N_VOX * C];          // x converted to fp16
__device__ int    g_nbrt[(size_t)N_VOX * 32];        // transposed neighbor table

static __device__ __forceinline__ __half2 as_h2(unsigned u) {
    return *reinterpret_cast<__half2*>(&u);
}

// ---------------------------------------------------------------------------
// Prep: transpose nbr[K,N] -> nbr_t[N,32] (pad 27..31 with -1) AND convert
// x fp32 -> fp16. N_VOX = 12500*32 exactly, so no bounds checks needed.
// ---------------------------------------------------------------------------
__global__ void __launch_bounds__(256)
prep_kernel(const int* __restrict__ nbr, int* __restrict__ nbrt,
            const float* __restrict__ x, __half* __restrict__ x16)
{
    __shared__ int tile[32][33];
    const int i0 = blockIdx.x * 32;
    const int x_ = threadIdx.x, ty = threadIdx.y;        // 32 x 8
    const int tid = ty * 32 + x_;
    const int i = i0 + x_;

    int v[4];
    #pragma unroll
    for (int j = 0; j < 4; ++j) {
        const int k = ty + j * 8;
        v[j] = (k < K_TAPS) ? nbr[k * N_VOX + i] : -1;
    }
    #pragma unroll
    for (int j = 0; j < 4; ++j) tile[ty + j * 8][x_] = v[j];

    // fp32 -> fp16 convert of this block's 32 voxel rows (1024 floats).
    const size_t base = (size_t)i0 * 32;
    #pragma unroll
    for (int j = 0; j < 4; ++j) {
        const int t = tid + j * 256;
        x16[base + t] = __float2half_rn(x[base + t]);
    }

    __syncthreads();
    #pragma unroll
    for (int j = 0; j < 4; ++j) {
        const int iv = i0 + ty + j * 8;
        nbrt[(size_t)iv * 32 + x_] = tile[x_][ty + j * 8];
    }
}

// ---------------------------------------------------------------------------
// Fused sparse-conv + LayerNorm + activation. One warp per voxel, lane = cout.
// fp16 activations (4x LDG.128/tap) + fp16 smem W (4x LDS.128/tap).
// Per tap: 16 HFMA2 into 8 fp16 partials (<=2 terms each -> tiny fp16 rounding),
// folded to fp32 accumulators every tap. LN + epilogue fp32.
// RESID=false writes fp16 h; RESID=true writes fp32 out.
// ---------------------------------------------------------------------------
template <bool RESID>
__global__ void __launch_bounds__(512)
conv_ln_kernel(const __half* __restrict__ in,       // [N,32] fp16
               const int*    __restrict__ nbrt,
               const float*  __restrict__ W,        // [27,32,32] fp32 (cin-major)
               const float*  __restrict__ gamma,
               const float*  __restrict__ beta,
               const float*  __restrict__ resid,    // fp32 (RESID only)
               __half*       __restrict__ outH,     // !RESID
               float*        __restrict__ outF)     // RESID
{
    extern __shared__ __half ws[];

    // Preload + convert + transpose: ws[(k*32+cout)*40 + cin] = half(W[k][cin][cout])
    for (int t = threadIdx.x; t < K_TAPS * 1024; t += blockDim.x) {
        const int k = t >> 10, r = t & 1023, cin = r >> 5, cout = r & 31;
        ws[(k * 32 + cout) * W_PITCH_H + cin] = __float2half_rn(W[t]);
    }
    __syncthreads();

    const int lane       = threadIdx.x & 31;
    const int warp_gid   = (blockIdx.x * blockDim.x + threadIdx.x) >> 5;
    const int warp_total = (gridDim.x * blockDim.x) >> 5;
    const float gm = gamma[lane];
    const float bt = beta[lane];

    for (int i = warp_gid; i < N_VOX; i += warp_total) {
        const int idx_l = nbrt[(size_t)i * 32 + lane];   // one coalesced line

        float fa0 = 0.0f, fa1 = 0.0f, fb0 = 0.0f, fb1 = 0.0f;
        unsigned m = __ballot_sync(FULL, idx_l >= 0);
        while (m) {
            const int k = __ffs(m) - 1;
            m &= m - 1;
            const int idx = __shfl_sync(FULL, idx_l, k);

            const uint4* __restrict__ xr =
                reinterpret_cast<const uint4*>(in + (size_t)idx * C);   // 64B row
            const uint4* __restrict__ wr =
                reinterpret_cast<const uint4*>(ws + (k * 32 + lane) * W_PITCH_H);

            // Full 32-channel dot product: 4 uint4 of x, 4 uint4 of W.
            const uint4 xv0 = xr[0], xv1 = xr[1], xv2 = xr[2], xv3 = xr[3];
            const uint4 wv0 = wr[0], wv1 = wr[1], wv2 = wr[2], wv3 = wr[3];

            const __half2 z = __float2half2_rn(0.0f);
            // 8 partials, <=2 products each (pairs of uint4: {0,1} and {2,3}).
            __half2 p0 = __hfma2(as_h2(xv0.x), as_h2(wv0.x), z);
            __half2 p1 = __hfma2(as_h2(xv0.y), as_h2(wv0.y), z);
            __half2 p2 = __hfma2(as_h2(xv0.z), as_h2(wv0.z), z);
            __half2 p3 = __hfma2(as_h2(xv0.w), as_h2(wv0.w), z);
            __half2 p4 = __hfma2(as_h2(xv2.x), as_h2(wv2.x), z);
            __half2 p5 = __hfma2(as_h2(xv2.y), as_h2(wv2.y), z);
            __half2 p6 = __hfma2(as_h2(xv2.z), as_h2(wv2.z), z);
            __half2 p7 = __hfma2(as_h2(xv2.w), as_h2(wv2.w), z);
            p0 = __hfma2(as_h2(xv1.x), as_h2(wv1.x), p0);
            p1 = __hfma2(as_h2(xv1.y), as_h2(wv1.y), p1);
            p2 = __hfma2(as_h2(xv1.z), as_h2(wv1.z), p2);
            p3 = __hfma2(as_h2(xv1.w), as_h2(wv1.w), p3);
            p4 = __hfma2(as_h2(xv3.x), as_h2(wv3.x), p4);
            p5 = __hfma2(as_h2(xv3.y), as_h2(wv3.y), p5);
            p6 = __hfma2(as_h2(xv3.z), as_h2(wv3.z), p6);
            p7 = __hfma2(as_h2(xv3.w), as_h2(wv3.w), p7);

            // Fold all 16 fp16 lanes into fp32 accumulators (fma pipe has headroom).
            const float2 f0 = __half22float2(p0), f1 = __half22float2(p1);
            const float2 f2 = __half22float2(p2), f3 = __half22float2(p3);
            const float2 f4 = __half22float2(p4), f5 = __half22float2(p5);
            const float2 f6 = __half22float2(p6), f7 = __half22float2(p7);
            fa0 += (f0.x + f1.x) + (f4.x + f5.x);
            fa1 += (f0.y + f1.y) + (f4.y + f5.y);
            fb0 += (f2.x + f3.x) + (f6.x + f7.x);
            fb1 += (f2.y + f3.y) + (f6.y + f7.y);
        }
        const float h = (fa0 + fa1) + (fb0 + fb1);

        // LayerNorm over the 32 channels (lanes), fp32.
        float s = h, s2 = h * h;
        #pragma unroll
        for (int o = 16; o; o >>= 1) {
            s  += __shfl_xor_sync(FULL, s,  o);
            s2 += __shfl_xor_sync(FULL, s2, o);
        }
        const float mu  = s  * 0.03125f;
        const float var = s2 * 0.03125f - mu * mu;
        float y = (h - mu) * rsqrtf(var + 1e-6f) * gm + bt;

        if (RESID) {
            y += resid[(size_t)i * C + lane];
            outF[(size_t)i * C + lane] = fmaxf(y, 0.0f);
        } else {
            outH[(size_t)i * C + lane] = __float2half_rn(fmaxf(y, 0.0f));
        }
    }
}

extern "C" void kernel_launch(void* const* d_in, const int* in_sizes, int n_in,
                              void* d_out, int out_size)
{
    const float* x   = (const float*)d_in[0];  // [N, 32]
    const int*   nbr = (const int*)  d_in[1];  // [27, N]
    const float* W1  = (const float*)d_in[2];  // [27, 32, 32]
    const float* g1  = (const float*)d_in[3];
    const float* b1  = (const float*)d_in[4];
    const float* W2  = (const float*)d_in[5];
    const float* g2  = (const float*)d_in[6];
    const float* b2  = (const float*)d_in[7];
    float* out = (float*)d_out;

    __half* h_buf = nullptr;
    __half* x16   = nullptr;
    int*    nbrt  = nullptr;
    cudaGetSymbolAddress((void**)&h_buf, g_h);
    cudaGetSymbolAddress((void**)&x16,   g_x16);
    cudaGetSymbolAddress((void**)&nbrt,  g_nbrt);

    cudaFuncSetAttribute(conv_ln_kernel<false>,
                         cudaFuncAttributeMaxDynamicSharedMemorySize, SMEM_W_BYTES);
    cudaFuncSetAttribute(conv_ln_kernel<true>,
                         cudaFuncAttributeMaxDynamicSharedMemorySize, SMEM_W_BYTES);

    // 1) Transpose neighbor table + convert x to fp16.
    prep_kernel<<<N_VOX / 32, dim3(32, 8)>>>(nbr, nbrt, x, x16);

    // 2) Block 1: h = relu(LN(conv(x16, W1)))  -> fp16
    conv_ln_kernel<false><<<444, 512, SMEM_W_BYTES>>>(x16, nbrt, W1, g1, b1,
                                                      nullptr, h_buf, nullptr);

    // 3) Block 2: out = relu(LN(conv(h, W2)) + x)  -> fp32
    conv_ln_kernel<true ><<<444, 512, SMEM_W_BYTES>>>(h_buf, nbrt, W2, g2, b2,
                                                      x, nullptr, out);
}